// round 15
// baseline (speedup 1.0000x reference)
#include <cuda_runtime.h>
#include <cuda_bf16.h>
#include <cuda_fp16.h>

#define N_U 100000
#define N_I 50000
#define D   128
#define N_E 1600000

#define SL_U 96
#define SL_I 128

#define KSH 136                              // fp16 smem row stride (128 + 8 pad)
#define TILE_H (128 * KSH)                   // halves per tile
#define SMEM_BYTES (3 * TILE_H * 2)          // sS + sX + sW = 104,448 B -> 2 blocks/SM

#define FB_U ((N_U + 127) / 128)   // 782
#define FB_I ((N_I + 127) / 128)   // 391
#define FB_T (FB_U + FB_I)

// scatter+convert launch block split
#define SC_B  ((N_E + 255) / 256)           // 6250 scatter
#define CU_B  (N_U * (D / 4) / 256)         // 12500 cvt xu (float4/thread)
#define CI_B  (N_I * (D / 4) / 256)         // 6250  cvt xi
#define CW_B  ((4 * D * D / 4) / 256)       // 64    cvt 4 W matrices
#define SCV_B (SC_B + CU_B + CI_B + CW_B)

// ---------------- scratch ----------------
__device__ __half g_xu_h[(size_t)N_U * D];     // fp16 x copies (gather src + MMA A)
__device__ __half g_xi_h[(size_t)N_I * D];
__device__ __half g_W_h[4][D * D];             // fp16 W_uu, W_iu, W_ii, W_ui
__device__ int    g_cnt_arr_u[N_U];
__device__ int    g_cnt_arr_i[N_I];
__device__ int2   g_pairs_u[(size_t)N_U * SL_U];
__device__ int2   g_pairs_i[(size_t)N_I * SL_I];
__device__ double g_loss_u, g_loss_i;
__device__ unsigned int g_cnt_u, g_cnt_i;

__device__ __forceinline__ uint2 f4_to_h4(float4 v) {
    __half2 lo = __float22half2_rn(make_float2(v.x, v.y));
    __half2 hi = __float22half2_rn(make_float2(v.z, v.w));
    return make_uint2(*(unsigned*)&lo, *(unsigned*)&hi);
}

// ---------------- zero ----------------
__global__ void zero_kernel() {
    int idx = blockIdx.x * blockDim.x + threadIdx.x;
    if (idx < N_U) g_cnt_arr_u[idx] = 0;
    if (idx < N_I) g_cnt_arr_i[idx] = 0;
    if (idx == 0) { g_loss_u = 0.0; g_loss_i = 0.0; g_cnt_u = 0u; g_cnt_i = 0u; }
}

// ---------------- scatter + fp16 pre-conversion (one launch) ----------------
__global__ __launch_bounds__(256) void scatter_cvt_kernel(
    const int* __restrict__ u_idx, const int* __restrict__ i_idx,
    const float* __restrict__ vals,
    const float* __restrict__ xu, const float* __restrict__ xi,
    const float* __restrict__ W_uu, const float* __restrict__ W_iu,
    const float* __restrict__ W_ii, const float* __restrict__ W_ui)
{
    const int b = blockIdx.x;
    if (b < SC_B) {
        int e = b * 256 + threadIdx.x;
        if (e >= N_E) return;
        const int u = u_idx[e];
        const int i = i_idx[e];
        const int vb = __float_as_int(vals[e]);
        int su = atomicAdd(&g_cnt_arr_u[u], 1);
        if (su < SL_U) g_pairs_u[(size_t)u * SL_U + su] = make_int2(i, vb);
        int si = atomicAdd(&g_cnt_arr_i[i], 1);
        if (si < SL_I) g_pairs_i[(size_t)i * SL_I + si] = make_int2(u, vb);
    } else if (b < SC_B + CU_B) {
        int idx = (b - SC_B) * 256 + threadIdx.x;
        ((uint2*)g_xu_h)[idx] = f4_to_h4(((const float4*)xu)[idx]);
    } else if (b < SC_B + CU_B + CI_B) {
        int idx = (b - SC_B - CU_B) * 256 + threadIdx.x;
        ((uint2*)g_xi_h)[idx] = f4_to_h4(((const float4*)xi)[idx]);
    } else {
        int idx = (b - SC_B - CU_B - CI_B) * 256 + threadIdx.x;  // over 4*D*D/4
        const int per = D * D / 4;   // float4 per matrix
        const int m = idx / per, r = idx % per;
        const float* W = (m == 0) ? W_uu : (m == 1) ? W_iu : (m == 2) ? W_ii : W_ui;
        ((uint2*)g_W_h[m])[r] = f4_to_h4(((const float4*)W)[r]);
    }
}

// ---------------- gather helpers ----------------
__device__ __forceinline__ void h4_fma(float4& acc, float v, uint2 h) {
    float2 lo = __half22float2(*(__half2*)&h.x);
    float2 hi = __half22float2(*(__half2*)&h.y);
    acc.x = fmaf(v, lo.x, acc.x);
    acc.y = fmaf(v, lo.y, acc.y);
    acc.z = fmaf(v, hi.x, acc.z);
    acc.w = fmaf(v, hi.y, acc.w);
}

// ---------------- fused: per-tile gather (smem) + FP16 dual GEMM ----------------
#define CP_ASYNC16(dst_u32, src_ptr) \
    asm volatile("cp.async.ca.shared.global [%0], [%1], 16;" \
                 :: "r"(dst_u32), "l"(src_ptr) : "memory")
#define CP_COMMIT() asm volatile("cp.async.commit_group;" ::: "memory")
#define CP_WAIT0()  asm volatile("cp.async.wait_group 0;" ::: "memory")

__global__ __launch_bounds__(256, 2) void gather_fused_all(
    const float* __restrict__ xu, const float* __restrict__ xi,
    const float* __restrict__ b_uu, const float* __restrict__ b_ii,
    float* __restrict__ out_xu, float* __restrict__ out_xi)
{
    extern __shared__ __half smemh[];
    __half* sS = smemh;                 // [128][KSH] gathered s tile (fp16)
    __half* sX = smemh + TILE_H;        // [128][KSH] x tile
    __half* sW = smemh + 2 * TILE_H;    // [128][KSH] W tile
    __shared__ float srs[128];          // per-row rowsum (mask)

    const int b = blockIdx.x;
    const float *x, *bias;
    const __half *xh, *gsrc, *WsH, *WcH;
    const int2* pairs; const int* cntarr;
    float* out; double* gloss; unsigned int* gcnt; int n_rows, cb, sl;
    if (b < FB_U) {
        x = xu; xh = g_xu_h; gsrc = g_xi_h; pairs = g_pairs_u; cntarr = g_cnt_arr_u;
        WsH = g_W_h[0]; WcH = g_W_h[1]; bias = b_uu;
        out = out_xu; gloss = &g_loss_u; gcnt = &g_cnt_u;
        n_rows = N_U; cb = b; sl = SL_U;
    } else {
        x = xi; xh = g_xi_h; gsrc = g_xu_h; pairs = g_pairs_i; cntarr = g_cnt_arr_i;
        WsH = g_W_h[2]; WcH = g_W_h[3]; bias = b_ii;
        out = out_xi; gloss = &g_loss_i; gcnt = &g_cnt_i;
        n_rows = N_I; cb = b - FB_U; sl = SL_I;
    }

    const int tid  = threadIdx.x;
    const int lane = tid & 31;
    const int warp = tid >> 5;
    const int row0 = cb * 128;

    // ---- phase 1: gather this tile's 128 rows into sS (fp16), rowsums into srs ----
    for (int k = 0; k < 16; ++k) {
        const int r  = warp * 16 + k;
        const int gr = row0 + r;
        float4 acc = make_float4(0.f, 0.f, 0.f, 0.f);
        float rs = 0.f;
        if (gr < n_rows) {
            int cnt = cntarr[gr];
            if (cnt > sl) cnt = sl;
            const size_t base = (size_t)gr * sl;
            int j = 0;
            for (; j + 4 <= cnt; j += 4) {
                const int2 p0 = pairs[base + j];
                const int2 p1 = pairs[base + j + 1];
                const int2 p2 = pairs[base + j + 2];
                const int2 p3 = pairs[base + j + 3];
                const float v0 = __int_as_float(p0.y);
                const float v1 = __int_as_float(p1.y);
                const float v2 = __int_as_float(p2.y);
                const float v3 = __int_as_float(p3.y);
                const uint2 h0 = ((const uint2*)(gsrc + (size_t)p0.x * D))[lane];
                const uint2 h1 = ((const uint2*)(gsrc + (size_t)p1.x * D))[lane];
                const uint2 h2 = ((const uint2*)(gsrc + (size_t)p2.x * D))[lane];
                const uint2 h3 = ((const uint2*)(gsrc + (size_t)p3.x * D))[lane];
                h4_fma(acc, v0, h0);
                h4_fma(acc, v1, h1);
                h4_fma(acc, v2, h2);
                h4_fma(acc, v3, h3);
                rs += (v0 + v1) + (v2 + v3);
            }
            for (; j < cnt; ++j) {
                const int2 p = pairs[base + j];
                const float v = __int_as_float(p.y);
                const uint2 h = ((const uint2*)(gsrc + (size_t)p.x * D))[lane];
                h4_fma(acc, v, h);
                rs += v;
            }
        }
        ((uint2*)(sS + r * KSH))[lane] = f4_to_h4(acc);
        if (lane == 0) srs[r] = rs;
    }

    // ---- phase 2: dual GEMM ----
    const int g  = lane >> 2;
    const int t  = lane & 3;
    const int wm = warp >> 1;
    const int wn = warp & 1;
    const int wr0 = wm * 32;
    const int wc0 = wn * 64;

    const unsigned sx_base = (unsigned)__cvta_generic_to_shared(sX);
    const unsigned sw_base = (unsigned)__cvta_generic_to_shared(sW);

    float acc[2][8][4];
    #pragma unroll
    for (int mt = 0; mt < 2; ++mt)
        #pragma unroll
        for (int nt = 0; nt < 8; ++nt) {
            acc[mt][nt][0] = 0.f; acc[mt][nt][1] = 0.f;
            acc[mt][nt][2] = 0.f; acc[mt][nt][3] = 0.f;
        }

    // stage x tile + Ws (pass 0 operands); sS already holds pass-1 A
    for (int idx = tid; idx < 128 * 16; idx += 256) {
        int r = idx >> 4, c = idx & 15;
        int gr = row0 + r;
        if (gr >= n_rows) gr = n_rows - 1;   // clamp: garbage rows unused
        CP_ASYNC16(sx_base + r * (KSH * 2) + c * 16,
                   xh + (size_t)gr * D + c * 8);
    }
    for (int idx = tid; idx < 128 * 16; idx += 256) {
        int r = idx >> 4, c = idx & 15;
        CP_ASYNC16(sw_base + r * (KSH * 2) + c * 16,
                   WsH + (size_t)r * D + c * 8);
    }
    CP_COMMIT();
    CP_WAIT0();
    __syncthreads();   // staging + phase-1 gather writes all visible

    #pragma unroll
    for (int pass = 0; pass < 2; ++pass) {
        const __half* sA = pass ? sS : sX;
        if (pass) {
            __syncthreads();   // pass-0 MMA done with sW
            for (int idx = tid; idx < 128 * 16; idx += 256) {
                int r = idx >> 4, c = idx & 15;
                CP_ASYNC16(sw_base + r * (KSH * 2) + c * 16,
                           WcH + (size_t)r * D + c * 8);
            }
            CP_COMMIT();
            CP_WAIT0();
            __syncthreads();
        }

        #pragma unroll
        for (int kt = 0; kt < 8; ++kt) {
            const int k0 = kt * 16;
            unsigned a[2][4];
            #pragma unroll
            for (int mt = 0; mt < 2; ++mt) {
                const int rr = wr0 + mt * 16 + g;
                a[mt][0] = *(const unsigned*)(sA + rr       * KSH + k0 + 2 * t);
                a[mt][1] = *(const unsigned*)(sA + (rr + 8) * KSH + k0 + 2 * t);
                a[mt][2] = *(const unsigned*)(sA + rr       * KSH + k0 + 2 * t + 8);
                a[mt][3] = *(const unsigned*)(sA + (rr + 8) * KSH + k0 + 2 * t + 8);
            }
            #pragma unroll
            for (int nt = 0; nt < 8; ++nt) {
                const int cr = wc0 + nt * 8 + g;
                unsigned b0 = *(const unsigned*)(sW + cr * KSH + k0 + 2 * t);
                unsigned b1 = *(const unsigned*)(sW + cr * KSH + k0 + 2 * t + 8);
                #pragma unroll
                for (int mt = 0; mt < 2; ++mt) {
                    asm volatile(
                        "mma.sync.aligned.m16n8k16.row.col.f32.f16.f16.f32 "
                        "{%0,%1,%2,%3},{%4,%5,%6,%7},{%8,%9},{%0,%1,%2,%3};"
                        : "+f"(acc[mt][nt][0]), "+f"(acc[mt][nt][1]),
                          "+f"(acc[mt][nt][2]), "+f"(acc[mt][nt][3])
                        : "r"(a[mt][0]), "r"(a[mt][1]), "r"(a[mt][2]), "r"(a[mt][3]),
                          "r"(b0), "r"(b1));
                }
            }
        }
    }

    // ---- epilogue: relu, mask (srs), residual, loss, mask count ----
    float sq = 0.f;
    int   cm = 0;
    #pragma unroll
    for (int mt = 0; mt < 2; ++mt) {
        const int lr0 = wr0 + mt * 16 + g;
        const int lr1 = lr0 + 8;
        const int r0 = row0 + lr0;
        const int r1 = row0 + lr1;
        const bool ok0 = r0 < n_rows;
        const bool ok1 = r1 < n_rows;
        const float m0 = (ok0 && srs[lr0] > 0.f) ? 1.f : 0.f;
        const float m1 = (ok1 && srs[lr1] > 0.f) ? 1.f : 0.f;
        if (wn == 0 && t == 0) cm += (int)m0 + (int)m1;
        #pragma unroll
        for (int nt = 0; nt < 8; ++nt) {
            const int cb2 = wc0 + nt * 8 + 2 * t;
            const float bx = bias[cb2];
            const float by = bias[cb2 + 1];
            if (ok0) {
                float dx = fmaxf(acc[mt][nt][0] + bx, 0.f) * m0;
                float dy = fmaxf(acc[mt][nt][1] + by, 0.f) * m0;
                sq += dx * dx + dy * dy;
                const float2 xv = *(const float2*)(x + (size_t)r0 * D + cb2);
                *(float2*)(out + (size_t)r0 * D + cb2) = make_float2(xv.x + dx, xv.y + dy);
            }
            if (ok1) {
                float dx = fmaxf(acc[mt][nt][2] + bx, 0.f) * m1;
                float dy = fmaxf(acc[mt][nt][3] + by, 0.f) * m1;
                sq += dx * dx + dy * dy;
                const float2 xv = *(const float2*)(x + (size_t)r1 * D + cb2);
                *(float2*)(out + (size_t)r1 * D + cb2) = make_float2(xv.x + dx, xv.y + dy);
            }
        }
    }

    #pragma unroll
    for (int off = 16; off; off >>= 1) {
        sq += __shfl_down_sync(0xffffffffu, sq, off);
        cm += __shfl_down_sync(0xffffffffu, cm, off);
    }
    if (lane == 0) {
        atomicAdd(gloss, (double)sq);
        if (cm) atomicAdd(gcnt, (unsigned)cm);
    }
}

// ---------------- final loss ----------------
__global__ void loss_kernel(float* __restrict__ out_loss) {
    double lu = (g_cnt_u > 0) ? g_loss_u / (double)g_cnt_u : 0.0;
    double li = (g_cnt_i > 0) ? g_loss_i / (double)g_cnt_i : 0.0;
    *out_loss = (float)(lu + li);
}

// ---------------- launch ----------------
extern "C" void kernel_launch(void* const* d_in, const int* in_sizes, int n_in,
                              void* d_out, int out_size)
{
    const float* xu    = (const float*)d_in[0];
    const float* xi    = (const float*)d_in[1];
    const int*   u_idx = (const int*)  d_in[2];
    const int*   i_idx = (const int*)  d_in[3];
    const float* vals  = (const float*)d_in[4];
    const float* W_uu  = (const float*)d_in[5];
    const float* b_uu  = (const float*)d_in[6];
    const float* W_ii  = (const float*)d_in[7];
    const float* b_ii  = (const float*)d_in[8];
    const float* W_iu  = (const float*)d_in[9];
    const float* W_ui  = (const float*)d_in[10];

    float* out      = (float*)d_out;
    float* out_xu   = out;
    float* out_xi   = out + (size_t)N_U * D;
    float* out_loss = out + (size_t)N_U * D + (size_t)N_I * D;

    cudaFuncSetAttribute(gather_fused_all,
                         cudaFuncAttributeMaxDynamicSharedMemorySize, SMEM_BYTES);

    zero_kernel<<<(N_U + 255) / 256, 256>>>();
    scatter_cvt_kernel<<<SCV_B, 256>>>(u_idx, i_idx, vals, xu, xi,
                                       W_uu, W_iu, W_ii, W_ui);
    gather_fused_all<<<FB_T, 256, SMEM_BYTES>>>(xu, xi, b_uu, b_ii,
                                                out_xu, out_xi);
    loss_kernel<<<1, 1>>>(out_loss);
}

// round 16
// speedup vs baseline: 1.5665x; 1.5665x over previous
#include <cuda_runtime.h>
#include <cuda_bf16.h>
#include <cuda_fp16.h>

#define N_U 100000
#define N_I 50000
#define D   128
#define N_E 1600000

#define SL_U 96
#define SL_I 128

#define KSH 136                          // fp16 smem row stride (128 + 8 pad)
#define SMEM_BYTES (2 * 128 * KSH * 2)   // 69,632 B -> 2 blocks/SM

#define GB_U (N_U / 16)                  // 6250 blocks: 8 warps x 2 rows
#define GB_I (N_I / 16)                  // 3125
#define GB_T (GB_U + GB_I)

#define FB_U ((N_U + 127) / 128)   // 782
#define FB_I ((N_I + 127) / 128)   // 391
#define FB_T (FB_U + FB_I)

// scatter+convert launch block split
#define SC_B  ((N_E + 255) / 256)           // 6250 scatter
#define CU_B  (N_U * (D / 4) / 256)         // 12500 cvt xu (float4/thread)
#define CI_B  (N_I * (D / 4) / 256)         // 6250  cvt xi
#define CW_B  ((4 * D * D / 4) / 256)       // 64    cvt 4 W matrices
#define SCV_B (SC_B + CU_B + CI_B + CW_B)

// ---------------- scratch ----------------
__device__ __half g_s_u_h[(size_t)N_U * D];    // fp16 message sums (MMA operand)
__device__ __half g_s_i_h[(size_t)N_I * D];
__device__ __half g_xu_h[(size_t)N_U * D];     // fp16 x copies (gather src + MMA A)
__device__ __half g_xi_h[(size_t)N_I * D];
__device__ __half g_W_h[4][D * D];             // fp16 W_uu, W_iu, W_ii, W_ui
__device__ int    g_cnt_arr_u[N_U];
__device__ int    g_cnt_arr_i[N_I];
__device__ int2   g_pairs_u[(size_t)N_U * SL_U];
__device__ int2   g_pairs_i[(size_t)N_I * SL_I];
__device__ float  g_rowsum_u[N_U];
__device__ float  g_rowsum_i[N_I];
__device__ double g_loss_u, g_loss_i;
__device__ unsigned int g_cnt_u, g_cnt_i;

__device__ __forceinline__ uint2 f4_to_h4(float4 v) {
    __half2 lo = __float22half2_rn(make_float2(v.x, v.y));
    __half2 hi = __float22half2_rn(make_float2(v.z, v.w));
    return make_uint2(*(unsigned*)&lo, *(unsigned*)&hi);
}

// ---------------- zero ----------------
__global__ void zero_kernel() {
    int idx = blockIdx.x * blockDim.x + threadIdx.x;
    if (idx < N_U) g_cnt_arr_u[idx] = 0;
    if (idx < N_I) g_cnt_arr_i[idx] = 0;
    if (idx == 0) { g_loss_u = 0.0; g_loss_i = 0.0; g_cnt_u = 0u; g_cnt_i = 0u; }
}

// ---------------- scatter + fp16 pre-conversion (one launch) ----------------
__global__ __launch_bounds__(256) void scatter_cvt_kernel(
    const int* __restrict__ u_idx, const int* __restrict__ i_idx,
    const float* __restrict__ vals,
    const float* __restrict__ xu, const float* __restrict__ xi,
    const float* __restrict__ W_uu, const float* __restrict__ W_iu,
    const float* __restrict__ W_ii, const float* __restrict__ W_ui)
{
    const int b = blockIdx.x;
    if (b < SC_B) {
        int e = b * 256 + threadIdx.x;
        if (e >= N_E) return;
        const int u = u_idx[e];
        const int i = i_idx[e];
        const int vb = __float_as_int(vals[e]);
        int su = atomicAdd(&g_cnt_arr_u[u], 1);
        if (su < SL_U) g_pairs_u[(size_t)u * SL_U + su] = make_int2(i, vb);
        int si = atomicAdd(&g_cnt_arr_i[i], 1);
        if (si < SL_I) g_pairs_i[(size_t)i * SL_I + si] = make_int2(u, vb);
    } else if (b < SC_B + CU_B) {
        int idx = (b - SC_B) * 256 + threadIdx.x;
        ((uint2*)g_xu_h)[idx] = f4_to_h4(((const float4*)xu)[idx]);
    } else if (b < SC_B + CU_B + CI_B) {
        int idx = (b - SC_B - CU_B) * 256 + threadIdx.x;
        ((uint2*)g_xi_h)[idx] = f4_to_h4(((const float4*)xi)[idx]);
    } else {
        int idx = (b - SC_B - CU_B - CI_B) * 256 + threadIdx.x;  // over 4*D*D/4
        const int per = D * D / 4;   // float4 per matrix
        const int m = idx / per, r = idx % per;
        const float* W = (m == 0) ? W_uu : (m == 1) ? W_iu : (m == 2) ? W_ii : W_ui;
        ((uint2*)g_W_h[m])[r] = f4_to_h4(((const float4*)W)[r]);
    }
}

// ---------------- gather: 2 rows per warp, interleaved (MLP 8) ----------------
__device__ __forceinline__ void h4_fma(float4& acc, float v, uint2 h) {
    float2 lo = __half22float2(*(__half2*)&h.x);
    float2 hi = __half22float2(*(__half2*)&h.y);
    acc.x = fmaf(v, lo.x, acc.x);
    acc.y = fmaf(v, lo.y, acc.y);
    acc.z = fmaf(v, hi.x, acc.z);
    acc.w = fmaf(v, hi.y, acc.w);
}

__device__ __forceinline__ void gather_range(
    float4& acc, float& rs, const __half* __restrict__ src,
    const int2* __restrict__ pairs, size_t base, int beg, int end, int lane)
{
    int j = beg;
    for (; j + 4 <= end; j += 4) {
        const int2 p0 = pairs[base + j];
        const int2 p1 = pairs[base + j + 1];
        const int2 p2 = pairs[base + j + 2];
        const int2 p3 = pairs[base + j + 3];
        const float v0 = __int_as_float(p0.y);
        const float v1 = __int_as_float(p1.y);
        const float v2 = __int_as_float(p2.y);
        const float v3 = __int_as_float(p3.y);
        const uint2 h0 = ((const uint2*)(src + (size_t)p0.x * D))[lane];
        const uint2 h1 = ((const uint2*)(src + (size_t)p1.x * D))[lane];
        const uint2 h2 = ((const uint2*)(src + (size_t)p2.x * D))[lane];
        const uint2 h3 = ((const uint2*)(src + (size_t)p3.x * D))[lane];
        h4_fma(acc, v0, h0);
        h4_fma(acc, v1, h1);
        h4_fma(acc, v2, h2);
        h4_fma(acc, v3, h3);
        rs += (v0 + v1) + (v2 + v3);
    }
    for (; j < end; ++j) {
        const int2 p = pairs[base + j];
        const float v = __int_as_float(p.y);
        const uint2 h = ((const uint2*)(src + (size_t)p.x * D))[lane];
        h4_fma(acc, v, h);
        rs += v;
    }
}

__global__ __launch_bounds__(256) void gather_all()
{
    const int b    = blockIdx.x;
    const int lane = threadIdx.x & 31;
    const int warp = threadIdx.x >> 5;

    const __half* src; const int2* pairs; const int* cntarr;
    __half* sdst; float* rowsum; int cb, sl;
    if (b < GB_U) {
        src = g_xi_h; pairs = g_pairs_u; cntarr = g_cnt_arr_u;
        sdst = g_s_u_h; rowsum = g_rowsum_u; cb = b; sl = SL_U;
    } else {
        src = g_xu_h; pairs = g_pairs_i; cntarr = g_cnt_arr_i;
        sdst = g_s_i_h; rowsum = g_rowsum_i; cb = b - GB_U; sl = SL_I;
    }

    // two consecutive rows per warp (rows always in range: exact division)
    const int rA = cb * 16 + warp * 2;
    const int rB = rA + 1;

    int cntA = cntarr[rA]; if (cntA > sl) cntA = sl;
    int cntB = cntarr[rB]; if (cntB > sl) cntB = sl;
    const size_t baseA = (size_t)rA * sl;
    const size_t baseB = (size_t)rB * sl;

    float4 accA = make_float4(0.f, 0.f, 0.f, 0.f);
    float4 accB = make_float4(0.f, 0.f, 0.f, 0.f);
    float rsA = 0.f, rsB = 0.f;

    // interleaved common part: 2 edges from each row per iteration (4 feature
    // loads + 4 pair loads in flight, two independent FMA chains)
    const int m = (cntA < cntB) ? cntA : cntB;
    int j = 0;
    for (; j + 2 <= m; j += 2) {
        const int2 pa0 = pairs[baseA + j];
        const int2 pa1 = pairs[baseA + j + 1];
        const int2 pb0 = pairs[baseB + j];
        const int2 pb1 = pairs[baseB + j + 1];
        const float va0 = __int_as_float(pa0.y);
        const float va1 = __int_as_float(pa1.y);
        const float vb0 = __int_as_float(pb0.y);
        const float vb1 = __int_as_float(pb1.y);
        const uint2 ha0 = ((const uint2*)(src + (size_t)pa0.x * D))[lane];
        const uint2 ha1 = ((const uint2*)(src + (size_t)pa1.x * D))[lane];
        const uint2 hb0 = ((const uint2*)(src + (size_t)pb0.x * D))[lane];
        const uint2 hb1 = ((const uint2*)(src + (size_t)pb1.x * D))[lane];
        h4_fma(accA, va0, ha0);
        h4_fma(accA, va1, ha1);
        h4_fma(accB, vb0, hb0);
        h4_fma(accB, vb1, hb1);
        rsA += va0 + va1;
        rsB += vb0 + vb1;
    }
    // tails (per-row order preserved)
    gather_range(accA, rsA, src, pairs, baseA, j, cntA, lane);
    gather_range(accB, rsB, src, pairs, baseB, j, cntB, lane);

    ((uint2*)(sdst + (size_t)rA * D))[lane] = f4_to_h4(accA);
    ((uint2*)(sdst + (size_t)rB * D))[lane] = f4_to_h4(accB);
    if (lane == 0) { rowsum[rA] = rsA; rowsum[rB] = rsB; }
}

// ---------------- fused FP16 dual GEMM via cp.async staging ----------------
#define CP_ASYNC16(dst_u32, src_ptr) \
    asm volatile("cp.async.ca.shared.global [%0], [%1], 16;" \
                 :: "r"(dst_u32), "l"(src_ptr) : "memory")
#define CP_COMMIT() asm volatile("cp.async.commit_group;" ::: "memory")
#define CP_WAIT0()  asm volatile("cp.async.wait_group 0;" ::: "memory")

__global__ __launch_bounds__(256, 2) void fused_all(
    const float* __restrict__ xu, const float* __restrict__ xi,
    const float* __restrict__ b_uu, const float* __restrict__ b_ii,
    float* __restrict__ out_xu, float* __restrict__ out_xi)
{
    extern __shared__ __half smemh[];
    __half* sX = smemh;                 // [128][KSH] fp16
    __half* sW = smemh + 128 * KSH;

    const int b = blockIdx.x;
    const float *x, *bias, *rowsum;
    const __half *xh, *sh, *WsH, *WcH;
    float* out; unsigned int* gcnt; int n_rows, cb; int is_user;
    if (b < FB_U) {
        x = xu; xh = g_xu_h; sh = g_s_u_h; WsH = g_W_h[0]; WcH = g_W_h[1];
        bias = b_uu; rowsum = g_rowsum_u; out = out_xu; gcnt = &g_cnt_u;
        n_rows = N_U; cb = b; is_user = 1;
    } else {
        x = xi; xh = g_xi_h; sh = g_s_i_h; WsH = g_W_h[2]; WcH = g_W_h[3];
        bias = b_ii; rowsum = g_rowsum_i; out = out_xi; gcnt = &g_cnt_i;
        n_rows = N_I; cb = b - FB_U; is_user = 0;
    }

    const int tid  = threadIdx.x;
    const int lane = tid & 31;
    const int warp = tid >> 5;
    const int g    = lane >> 2;
    const int t    = lane & 3;
    const int row0 = cb * 128;
    const int wm   = warp >> 1;
    const int wn   = warp & 1;
    const int wr0  = wm * 32;
    const int wc0  = wn * 64;

    const unsigned sx_base = (unsigned)__cvta_generic_to_shared(sX);
    const unsigned sw_base = (unsigned)__cvta_generic_to_shared(sW);

    float acc[2][8][4];
    #pragma unroll
    for (int mt = 0; mt < 2; ++mt)
        #pragma unroll
        for (int nt = 0; nt < 8; ++nt) {
            acc[mt][nt][0] = 0.f; acc[mt][nt][1] = 0.f;
            acc[mt][nt][2] = 0.f; acc[mt][nt][3] = 0.f;
        }

    #pragma unroll
    for (int pass = 0; pass < 2; ++pass) {
        const __half* srcH = pass ? sh  : xh;
        const __half* WH   = pass ? WcH : WsH;
        __syncthreads();   // previous MMA loop done with smem
        for (int idx = tid; idx < 128 * 16; idx += 256) {
            int r = idx >> 4, c = idx & 15;
            int gr = row0 + r;
            if (gr >= n_rows) gr = n_rows - 1;   // clamp: garbage rows unused
            CP_ASYNC16(sx_base + r * (KSH * 2) + c * 16,
                       srcH + (size_t)gr * D + c * 8);
        }
        for (int idx = tid; idx < 128 * 16; idx += 256) {
            int r = idx >> 4, c = idx & 15;
            CP_ASYNC16(sw_base + r * (KSH * 2) + c * 16,
                       WH + (size_t)r * D + c * 8);
        }
        CP_COMMIT();
        CP_WAIT0();
        __syncthreads();

        #pragma unroll
        for (int kt = 0; kt < 8; ++kt) {
            const int k0 = kt * 16;
            unsigned a[2][4];
            #pragma unroll
            for (int mt = 0; mt < 2; ++mt) {
                const int rr = wr0 + mt * 16 + g;
                a[mt][0] = *(const unsigned*)(sX + rr       * KSH + k0 + 2 * t);
                a[mt][1] = *(const unsigned*)(sX + (rr + 8) * KSH + k0 + 2 * t);
                a[mt][2] = *(const unsigned*)(sX + rr       * KSH + k0 + 2 * t + 8);
                a[mt][3] = *(const unsigned*)(sX + (rr + 8) * KSH + k0 + 2 * t + 8);
            }
            #pragma unroll
            for (int nt = 0; nt < 8; ++nt) {
                const int cr = wc0 + nt * 8 + g;
                unsigned b0 = *(const unsigned*)(sW + cr * KSH + k0 + 2 * t);
                unsigned b1 = *(const unsigned*)(sW + cr * KSH + k0 + 2 * t + 8);
                #pragma unroll
                for (int mt = 0; mt < 2; ++mt) {
                    asm volatile(
                        "mma.sync.aligned.m16n8k16.row.col.f32.f16.f16.f32 "
                        "{%0,%1,%2,%3},{%4,%5,%6,%7},{%8,%9},{%0,%1,%2,%3};"
                        : "+f"(acc[mt][nt][0]), "+f"(acc[mt][nt][1]),
                          "+f"(acc[mt][nt][2]), "+f"(acc[mt][nt][3])
                        : "r"(a[mt][0]), "r"(a[mt][1]), "r"(a[mt][2]), "r"(a[mt][3]),
                          "r"(b0), "r"(b1));
                }
            }
        }
    }

    float sq = 0.f;
    int   cm = 0;
    #pragma unroll
    for (int mt = 0; mt < 2; ++mt) {
        const int r0 = row0 + wr0 + mt * 16 + g;
        const int r1 = r0 + 8;
        const bool ok0 = r0 < n_rows;
        const bool ok1 = r1 < n_rows;
        const float m0 = (ok0 && rowsum[r0] > 0.f) ? 1.f : 0.f;
        const float m1 = (ok1 && rowsum[r1] > 0.f) ? 1.f : 0.f;
        if (wn == 0 && t == 0) cm += (int)m0 + (int)m1;
        #pragma unroll
        for (int nt = 0; nt < 8; ++nt) {
            const int cb2 = wc0 + nt * 8 + 2 * t;
            const float bx = bias[cb2];
            const float by = bias[cb2 + 1];
            if (ok0) {
                float dx = fmaxf(acc[mt][nt][0] + bx, 0.f) * m0;
                float dy = fmaxf(acc[mt][nt][1] + by, 0.f) * m0;
                sq += dx * dx + dy * dy;
                const float2 xv = *(const float2*)(x + (size_t)r0 * D + cb2);
                *(float2*)(out + (size_t)r0 * D + cb2) = make_float2(xv.x + dx, xv.y + dy);
            }
            if (ok1) {
                float dx = fmaxf(acc[mt][nt][2] + bx, 0.f) * m1;
                float dy = fmaxf(acc[mt][nt][3] + by, 0.f) * m1;
                sq += dx * dx + dy * dy;
                const float2 xv = *(const float2*)(x + (size_t)r1 * D + cb2);
                *(float2*)(out + (size_t)r1 * D + cb2) = make_float2(xv.x + dx, xv.y + dy);
            }
        }
    }

    #pragma unroll
    for (int off = 16; off; off >>= 1) {
        sq += __shfl_down_sync(0xffffffffu, sq, off);
        cm += __shfl_down_sync(0xffffffffu, cm, off);
    }
    if (lane == 0) {
        atomicAdd(is_user ? &g_loss_u : &g_loss_i, (double)sq);
        if (cm) atomicAdd(gcnt, (unsigned)cm);
    }
}

// ---------------- final loss ----------------
__global__ void loss_kernel(float* __restrict__ out_loss) {
    double lu = (g_cnt_u > 0) ? g_loss_u / (double)g_cnt_u : 0.0;
    double li = (g_cnt_i > 0) ? g_loss_i / (double)g_cnt_i : 0.0;
    *out_loss = (float)(lu + li);
}

// ---------------- launch ----------------
extern "C" void kernel_launch(void* const* d_in, const int* in_sizes, int n_in,
                              void* d_out, int out_size)
{
    const float* xu    = (const float*)d_in[0];
    const float* xi    = (const float*)d_in[1];
    const int*   u_idx = (const int*)  d_in[2];
    const int*   i_idx = (const int*)  d_in[3];
    const float* vals  = (const float*)d_in[4];
    const float* W_uu  = (const float*)d_in[5];
    const float* b_uu  = (const float*)d_in[6];
    const float* W_ii  = (const float*)d_in[7];
    const float* b_ii  = (const float*)d_in[8];
    const float* W_iu  = (const float*)d_in[9];
    const float* W_ui  = (const float*)d_in[10];

    float* out      = (float*)d_out;
    float* out_xu   = out;
    float* out_xi   = out + (size_t)N_U * D;
    float* out_loss = out + (size_t)N_U * D + (size_t)N_I * D;

    cudaFuncSetAttribute(fused_all,
                         cudaFuncAttributeMaxDynamicSharedMemorySize, SMEM_BYTES);

    zero_kernel<<<(N_U + 255) / 256, 256>>>();
    scatter_cvt_kernel<<<SCV_B, 256>>>(u_idx, i_idx, vals, xu, xi,
                                       W_uu, W_iu, W_ii, W_ui);
    gather_all<<<GB_T, 256>>>();
    fused_all<<<FB_T, 256, SMEM_BYTES>>>(xu, xi, b_uu, b_ii, out_xu, out_xi);
    loss_kernel<<<1, 1>>>(out_loss);
}

// round 17
// speedup vs baseline: 1.6679x; 1.0647x over previous
#include <cuda_runtime.h>
#include <cuda_bf16.h>
#include <cuda_fp16.h>

#define N_U 100000
#define N_I 50000
#define D   128
#define N_E 1600000

#define SL_U 96
#define SL_I 128

#define KSH 136                          // fp16 smem row stride (128 + 8 pad)
#define SMEM_BYTES (2 * 128 * KSH * 2)   // 69,632 B -> 2 blocks/SM

#define GB_U (N_U / 8)
#define GB_I (N_I / 8)
#define GB_T (GB_U + GB_I)

#define FB_U ((N_U + 127) / 128)   // 782
#define FB_I ((N_I + 127) / 128)   // 391
#define FB_T (FB_U + FB_I)

// scatter+convert launch block split
#define SC_B  ((N_E + 255) / 256)           // 6250 scatter
#define CU_B  (N_U * (D / 4) / 256)         // 12500 cvt xu (float4/thread)
#define CI_B  (N_I * (D / 4) / 256)         // 6250  cvt xi
#define CW_B  ((4 * D * D / 4) / 256)       // 64    cvt 4 W matrices
#define SCV_B (SC_B + CU_B + CI_B + CW_B)

// ---------------- scratch ----------------
__device__ __half g_s_u_h[(size_t)N_U * D];    // fp16 message sums (MMA operand)
__device__ __half g_s_i_h[(size_t)N_I * D];
__device__ __half g_xu_h[(size_t)N_U * D];     // fp16 x copies (gather src + MMA A + residual)
__device__ __half g_xi_h[(size_t)N_I * D];
__device__ __half g_W_h[4][D * D];             // fp16 W_uu, W_iu, W_ii, W_ui
__device__ int    g_cnt_arr_u[N_U];
__device__ int    g_cnt_arr_i[N_I];
__device__ int2   g_pairs_u[(size_t)N_U * SL_U];
__device__ int2   g_pairs_i[(size_t)N_I * SL_I];
__device__ float  g_rowsum_u[N_U];
__device__ float  g_rowsum_i[N_I];
__device__ double g_loss_u, g_loss_i;
__device__ unsigned int g_cnt_u, g_cnt_i;

__device__ __forceinline__ uint2 f4_to_h4(float4 v) {
    __half2 lo = __float22half2_rn(make_float2(v.x, v.y));
    __half2 hi = __float22half2_rn(make_float2(v.z, v.w));
    return make_uint2(*(unsigned*)&lo, *(unsigned*)&hi);
}

// ---------------- zero ----------------
__global__ void zero_kernel() {
    int idx = blockIdx.x * blockDim.x + threadIdx.x;
    if (idx < N_U) g_cnt_arr_u[idx] = 0;
    if (idx < N_I) g_cnt_arr_i[idx] = 0;
    if (idx == 0) { g_loss_u = 0.0; g_loss_i = 0.0; g_cnt_u = 0u; g_cnt_i = 0u; }
}

// ---------------- scatter + fp16 pre-conversion (one launch) ----------------
__global__ __launch_bounds__(256) void scatter_cvt_kernel(
    const int* __restrict__ u_idx, const int* __restrict__ i_idx,
    const float* __restrict__ vals,
    const float* __restrict__ xu, const float* __restrict__ xi,
    const float* __restrict__ W_uu, const float* __restrict__ W_iu,
    const float* __restrict__ W_ii, const float* __restrict__ W_ui)
{
    const int b = blockIdx.x;
    if (b < SC_B) {
        int e = b * 256 + threadIdx.x;
        if (e >= N_E) return;
        const int u = u_idx[e];
        const int i = i_idx[e];
        const int vb = __float_as_int(vals[e]);
        int su = atomicAdd(&g_cnt_arr_u[u], 1);
        if (su < SL_U) g_pairs_u[(size_t)u * SL_U + su] = make_int2(i, vb);
        int si = atomicAdd(&g_cnt_arr_i[i], 1);
        if (si < SL_I) g_pairs_i[(size_t)i * SL_I + si] = make_int2(u, vb);
    } else if (b < SC_B + CU_B) {
        int idx = (b - SC_B) * 256 + threadIdx.x;
        ((uint2*)g_xu_h)[idx] = f4_to_h4(((const float4*)xu)[idx]);
    } else if (b < SC_B + CU_B + CI_B) {
        int idx = (b - SC_B - CU_B) * 256 + threadIdx.x;
        ((uint2*)g_xi_h)[idx] = f4_to_h4(((const float4*)xi)[idx]);
    } else {
        int idx = (b - SC_B - CU_B - CI_B) * 256 + threadIdx.x;  // over 4*D*D/4
        const int per = D * D / 4;   // float4 per matrix
        const int m = idx / per, r = idx % per;
        const float* W = (m == 0) ? W_uu : (m == 1) ? W_iu : (m == 2) ? W_ii : W_ui;
        ((uint2*)g_W_h[m])[r] = f4_to_h4(((const float4*)W)[r]);
    }
}

// ---------------- gather: warp per dst row (R13 proven form) ----------------
__device__ __forceinline__ void h4_fma(float4& acc, float v, uint2 h) {
    float2 lo = __half22float2(*(__half2*)&h.x);
    float2 hi = __half22float2(*(__half2*)&h.y);
    acc.x = fmaf(v, lo.x, acc.x);
    acc.y = fmaf(v, lo.y, acc.y);
    acc.z = fmaf(v, hi.x, acc.z);
    acc.w = fmaf(v, hi.y, acc.w);
}

__global__ __launch_bounds__(256) void gather_all()
{
    const int b = blockIdx.x;
    const __half* src; const int2* pairs; const int* cntarr;
    __half* sdst; float* rowsum; int cb, sl;
    if (b < GB_U) {
        src = g_xi_h; pairs = g_pairs_u; cntarr = g_cnt_arr_u;
        sdst = g_s_u_h; rowsum = g_rowsum_u; cb = b; sl = SL_U;
    } else {
        src = g_xu_h; pairs = g_pairs_i; cntarr = g_cnt_arr_i;
        sdst = g_s_i_h; rowsum = g_rowsum_i; cb = b - GB_U; sl = SL_I;
    }

    const int lane = threadIdx.x & 31;
    const int warp = threadIdx.x >> 5;
    const int row  = cb * 8 + warp;

    int cnt = cntarr[row];
    if (cnt > sl) cnt = sl;
    const size_t base = (size_t)row * sl;

    float4 acc = make_float4(0.f, 0.f, 0.f, 0.f);
    float rs = 0.f;

    int j = 0;
    for (; j + 4 <= cnt; j += 4) {
        const int2 p0 = pairs[base + j];
        const int2 p1 = pairs[base + j + 1];
        const int2 p2 = pairs[base + j + 2];
        const int2 p3 = pairs[base + j + 3];
        const float v0 = __int_as_float(p0.y);
        const float v1 = __int_as_float(p1.y);
        const float v2 = __int_as_float(p2.y);
        const float v3 = __int_as_float(p3.y);
        const uint2 h0 = ((const uint2*)(src + (size_t)p0.x * D))[lane];
        const uint2 h1 = ((const uint2*)(src + (size_t)p1.x * D))[lane];
        const uint2 h2 = ((const uint2*)(src + (size_t)p2.x * D))[lane];
        const uint2 h3 = ((const uint2*)(src + (size_t)p3.x * D))[lane];
        h4_fma(acc, v0, h0);
        h4_fma(acc, v1, h1);
        h4_fma(acc, v2, h2);
        h4_fma(acc, v3, h3);
        rs += (v0 + v1) + (v2 + v3);
    }
    for (; j < cnt; ++j) {
        const int2 p = pairs[base + j];
        const float v = __int_as_float(p.y);
        const uint2 h = ((const uint2*)(src + (size_t)p.x * D))[lane];
        h4_fma(acc, v, h);
        rs += v;
    }

    ((uint2*)(sdst + (size_t)row * D))[lane] = f4_to_h4(acc);
    if (lane == 0) rowsum[row] = rs;
}

// ---------------- fused FP16 dual GEMM; residual from smem x tile ----------------
#define CP_ASYNC16(dst_u32, src_ptr) \
    asm volatile("cp.async.ca.shared.global [%0], [%1], 16;" \
                 :: "r"(dst_u32), "l"(src_ptr) : "memory")
#define CP_COMMIT() asm volatile("cp.async.commit_group;" ::: "memory")
#define CP_WAIT0()  asm volatile("cp.async.wait_group 0;" ::: "memory")

__global__ __launch_bounds__(256, 2) void fused_all(
    const float* __restrict__ b_uu, const float* __restrict__ b_ii,
    float* __restrict__ out_xu, float* __restrict__ out_xi)
{
    extern __shared__ __half smemh[];
    __half* sX = smemh;                 // [128][KSH] fp16 (holds x tile after pass 1)
    __half* sW = smemh + 128 * KSH;

    const int b = blockIdx.x;
    const float *bias, *rowsum;
    const __half *xh, *sh, *WsH, *WcH;
    float* out; unsigned int* gcnt; int n_rows, cb; int is_user;
    if (b < FB_U) {
        xh = g_xu_h; sh = g_s_u_h; WsH = g_W_h[0]; WcH = g_W_h[1];
        bias = b_uu; rowsum = g_rowsum_u; out = out_xu; gcnt = &g_cnt_u;
        n_rows = N_U; cb = b; is_user = 1;
    } else {
        xh = g_xi_h; sh = g_s_i_h; WsH = g_W_h[2]; WcH = g_W_h[3];
        bias = b_ii; rowsum = g_rowsum_i; out = out_xi; gcnt = &g_cnt_i;
        n_rows = N_I; cb = b - FB_U; is_user = 0;
    }

    const int tid  = threadIdx.x;
    const int lane = tid & 31;
    const int warp = tid >> 5;
    const int g    = lane >> 2;
    const int t    = lane & 3;
    const int row0 = cb * 128;
    const int wm   = warp >> 1;
    const int wn   = warp & 1;
    const int wr0  = wm * 32;
    const int wc0  = wn * 64;

    const unsigned sx_base = (unsigned)__cvta_generic_to_shared(sX);
    const unsigned sw_base = (unsigned)__cvta_generic_to_shared(sW);

    float acc[2][8][4];
    #pragma unroll
    for (int mt = 0; mt < 2; ++mt)
        #pragma unroll
        for (int nt = 0; nt < 8; ++nt) {
            acc[mt][nt][0] = 0.f; acc[mt][nt][1] = 0.f;
            acc[mt][nt][2] = 0.f; acc[mt][nt][3] = 0.f;
        }

    // pass 0: s @ Wc ; pass 1: x @ Ws  (x tile remains in sX for the epilogue)
    #pragma unroll
    for (int pass = 0; pass < 2; ++pass) {
        const __half* srcH = pass ? xh  : sh;
        const __half* WH   = pass ? WsH : WcH;
        __syncthreads();   // previous MMA loop done with smem
        for (int idx = tid; idx < 128 * 16; idx += 256) {
            int r = idx >> 4, c = idx & 15;
            int gr = row0 + r;
            if (gr >= n_rows) gr = n_rows - 1;   // clamp: garbage rows unused
            CP_ASYNC16(sx_base + r * (KSH * 2) + c * 16,
                       srcH + (size_t)gr * D + c * 8);
        }
        for (int idx = tid; idx < 128 * 16; idx += 256) {
            int r = idx >> 4, c = idx & 15;
            CP_ASYNC16(sw_base + r * (KSH * 2) + c * 16,
                       WH + (size_t)r * D + c * 8);
        }
        CP_COMMIT();
        CP_WAIT0();
        __syncthreads();

        #pragma unroll
        for (int kt = 0; kt < 8; ++kt) {
            const int k0 = kt * 16;
            unsigned a[2][4];
            #pragma unroll
            for (int mt = 0; mt < 2; ++mt) {
                const int rr = wr0 + mt * 16 + g;
                a[mt][0] = *(const unsigned*)(sX + rr       * KSH + k0 + 2 * t);
                a[mt][1] = *(const unsigned*)(sX + (rr + 8) * KSH + k0 + 2 * t);
                a[mt][2] = *(const unsigned*)(sX + rr       * KSH + k0 + 2 * t + 8);
                a[mt][3] = *(const unsigned*)(sX + (rr + 8) * KSH + k0 + 2 * t + 8);
            }
            #pragma unroll
            for (int nt = 0; nt < 8; ++nt) {
                const int cr = wc0 + nt * 8 + g;
                unsigned b0 = *(const unsigned*)(sW + cr * KSH + k0 + 2 * t);
                unsigned b1 = *(const unsigned*)(sW + cr * KSH + k0 + 2 * t + 8);
                #pragma unroll
                for (int mt = 0; mt < 2; ++mt) {
                    asm volatile(
                        "mma.sync.aligned.m16n8k16.row.col.f32.f16.f16.f32 "
                        "{%0,%1,%2,%3},{%4,%5,%6,%7},{%8,%9},{%0,%1,%2,%3};"
                        : "+f"(acc[mt][nt][0]), "+f"(acc[mt][nt][1]),
                          "+f"(acc[mt][nt][2]), "+f"(acc[mt][nt][3])
                        : "r"(a[mt][0]), "r"(a[mt][1]), "r"(a[mt][2]), "r"(a[mt][3]),
                          "r"(b0), "r"(b1));
                }
            }
        }
    }

    // epilogue: residual x read from the sX smem tile (fp16), no global x read
    float sq = 0.f;
    int   cm = 0;
    #pragma unroll
    for (int mt = 0; mt < 2; ++mt) {
        const int lr0 = wr0 + mt * 16 + g;
        const int lr1 = lr0 + 8;
        const int r0 = row0 + lr0;
        const int r1 = row0 + lr1;
        const bool ok0 = r0 < n_rows;
        const bool ok1 = r1 < n_rows;
        const float m0 = (ok0 && rowsum[r0] > 0.f) ? 1.f : 0.f;
        const float m1 = (ok1 && rowsum[r1] > 0.f) ? 1.f : 0.f;
        if (wn == 0 && t == 0) cm += (int)m0 + (int)m1;
        #pragma unroll
        for (int nt = 0; nt < 8; ++nt) {
            const int cb2 = wc0 + nt * 8 + 2 * t;
            const float bx = bias[cb2];
            const float by = bias[cb2 + 1];
            if (ok0) {
                float dx = fmaxf(acc[mt][nt][0] + bx, 0.f) * m0;
                float dy = fmaxf(acc[mt][nt][1] + by, 0.f) * m0;
                sq += dx * dx + dy * dy;
                const float2 xv = __half22float2(*(const __half2*)(sX + lr0 * KSH + cb2));
                *(float2*)(out + (size_t)r0 * D + cb2) = make_float2(xv.x + dx, xv.y + dy);
            }
            if (ok1) {
                float dx = fmaxf(acc[mt][nt][2] + bx, 0.f) * m1;
                float dy = fmaxf(acc[mt][nt][3] + by, 0.f) * m1;
                sq += dx * dx + dy * dy;
                const float2 xv = __half22float2(*(const __half2*)(sX + lr1 * KSH + cb2));
                *(float2*)(out + (size_t)r1 * D + cb2) = make_float2(xv.x + dx, xv.y + dy);
            }
        }
    }

    #pragma unroll
    for (int off = 16; off; off >>= 1) {
        sq += __shfl_down_sync(0xffffffffu, sq, off);
        cm += __shfl_down_sync(0xffffffffu, cm, off);
    }
    if (lane == 0) {
        atomicAdd(is_user ? &g_loss_u : &g_loss_i, (double)sq);
        if (cm) atomicAdd(gcnt, (unsigned)cm);
    }
}

// ---------------- final loss ----------------
__global__ void loss_kernel(float* __restrict__ out_loss) {
    double lu = (g_cnt_u > 0) ? g_loss_u / (double)g_cnt_u : 0.0;
    double li = (g_cnt_i > 0) ? g_loss_i / (double)g_cnt_i : 0.0;
    *out_loss = (float)(lu + li);
}

// ---------------- launch ----------------
extern "C" void kernel_launch(void* const* d_in, const int* in_sizes, int n_in,
                              void* d_out, int out_size)
{
    const float* xu    = (const float*)d_in[0];
    const float* xi    = (const float*)d_in[1];
    const int*   u_idx = (const int*)  d_in[2];
    const int*   i_idx = (const int*)  d_in[3];
    const float* vals  = (const float*)d_in[4];
    const float* W_uu  = (const float*)d_in[5];
    const float* b_uu  = (const float*)d_in[6];
    const float* W_ii  = (const float*)d_in[7];
    const float* b_ii  = (const float*)d_in[8];
    const float* W_iu  = (const float*)d_in[9];
    const float* W_ui  = (const float*)d_in[10];

    float* out      = (float*)d_out;
    float* out_xu   = out;
    float* out_xi   = out + (size_t)N_U * D;
    float* out_loss = out + (size_t)N_U * D + (size_t)N_I * D;

    cudaFuncSetAttribute(fused_all,
                         cudaFuncAttributeMaxDynamicSharedMemorySize, SMEM_BYTES);

    zero_kernel<<<(N_U + 255) / 256, 256>>>();
    scatter_cvt_kernel<<<SCV_B, 256>>>(u_idx, i_idx, vals, xu, xi,
                                       W_uu, W_iu, W_ii, W_ui);
    gather_all<<<GB_T, 256>>>();
    fused_all<<<FB_T, 256, SMEM_BYTES>>>(b_uu, b_ii, out_xu, out_xi);
    loss_kernel<<<1, 1>>>(out_loss);
}